// round 9
// baseline (speedup 1.0000x reference)
#include <cuda_runtime.h>
#include <cuda_bf16.h>
#include <math.h>

#define Bn    8
#define Ln    2048
#define KSEL  64
#define EXCL  3
#define NAA   20
#define EMB   16
#define MD    7
#define D2CUT 144.0f      // r >= 12 -> smoothstep == 0 -> zero energy
#define BCAP  256         // bucket capacity before radix fallback
#define BINSCALE (256.0f / 144.0f)

// Scratch (device globals: no allocation allowed)
__device__ float g_Rx[Bn * Ln];
__device__ float g_Ry[Bn * Ln];
__device__ float g_Rz[Bn * Ln];
__device__ float g_rowsum[Bn * Ln];
__device__ float g_tab[NAA * NAA * MD];       // softplus(MLP(aa_i,aa_j))

// Packed f32x2 helpers (Blackwell dual-FMA pipe)
#define PACK2(out, lo, hi) \
    asm("mov.b64 %0, {%1, %2};" : "=l"(out) : "f"(lo), "f"(hi))
#define UNPACK2(lo, hi, in) \
    asm("mov.b64 {%0, %1}, %2;" : "=f"(lo), "=f"(hi) : "l"(in))
#define ADD2(out, a, b) \
    asm("add.rn.f32x2 %0, %1, %2;" : "=l"(out) : "l"(a), "l"(b))
#define FMA2(out, a, b, c) \
    asm("fma.rn.f32x2 %0, %1, %2, %3;" : "=l"(out) : "l"(a), "l"(b), "l"(c))

// ---------------------------------------------------------------------------
// Kernel T: AoS -> SoA transpose of R (once; R is L2-resident)
// ---------------------------------------------------------------------------
__global__ void __launch_bounds__(256) transpose_kernel(const float* __restrict__ R)
{
    int p = blockIdx.x * 256 + threadIdx.x;
    float x = R[3 * p + 0];
    float y = R[3 * p + 1];
    float z = R[3 * p + 2];
    g_Rx[p] = x; g_Ry[p] = y; g_Rz[p] = z;
}

// ---------------------------------------------------------------------------
// Kernel 0: exact fp32 MLP over 400 AA pairs -> 400x7 table.
// 2 pairs/block (ILP-2), 512 threads, 4-way K-split (short serial chains).
// ---------------------------------------------------------------------------
__global__ void __launch_bounds__(512) table_kernel(
    const float* __restrict__ emb,
    const float* __restrict__ W1, const float* __restrict__ b1,
    const float* __restrict__ W2, const float* __restrict__ b2,
    const float* __restrict__ W3, const float* __restrict__ b3)
{
    __shared__ float x[2][48];
    __shared__ float h1[2][128];
    __shared__ float h2[2][128];
    __shared__ float part[2][4][128];

    const int p0 = blockIdx.x * 2;
    const int tid = threadIdx.x;
    const int n = tid & 127;
    const int q4 = tid >> 7;            // 0..3

    if (tid < 2 * EMB) {
        int pr = tid >> 4, c = tid & 15;
        int p = p0 + pr;
        float ei = emb[(p / NAA) * EMB + c];
        float ej = emb[(p % NAA) * EMB + c];
        x[pr][c] = ei; x[pr][EMB + c] = ej; x[pr][2 * EMB + c] = ei * ej;
    }
    __syncthreads();

    {   // Layer 1: K=48, 4 x 12
        float a0 = 0.f, a1 = 0.f;
        const int k0 = q4 * 12;
        #pragma unroll
        for (int k = 0; k < 12; k++) {
            float w = W1[(k0 + k) * 128 + n];
            a0 = fmaf(x[0][k0 + k], w, a0);
            a1 = fmaf(x[1][k0 + k], w, a1);
        }
        part[0][q4][n] = a0; part[1][q4][n] = a1;
    }
    __syncthreads();
    if (q4 < 2)
        h1[q4][n] = fmaxf(b1[n] + part[q4][0][n] + part[q4][1][n]
                                + part[q4][2][n] + part[q4][3][n], 0.f);
    __syncthreads();

    {   // Layer 2: K=128, 4 x 32
        float a0 = 0.f, a1 = 0.f;
        const int k0 = q4 * 32;
        #pragma unroll
        for (int k = 0; k < 32; k++) {
            float w = W2[(k0 + k) * 128 + n];
            a0 = fmaf(h1[0][k0 + k], w, a0);
            a1 = fmaf(h1[1][k0 + k], w, a1);
        }
        part[0][q4][n] = a0; part[1][q4][n] = a1;
    }
    __syncthreads();
    if (q4 < 2)
        h2[q4][n] = fmaxf(b2[n] + part[q4][0][n] + part[q4][1][n]
                                + part[q4][2][n] + part[q4][3][n], 0.f);
    __syncthreads();

    if (tid < 2 * MD * 4) {   // Layer 3: K=128, 4 x 32, 7 outs x 2 pairs
        int pr = tid / 28, rem = tid % 28;
        int m = rem % MD, qq = rem / MD;
        float a = 0.f;
        const int k0 = qq * 32;
        #pragma unroll
        for (int k = 0; k < 32; k++)
            a = fmaf(h2[pr][k0 + k], W3[(k0 + k) * MD + m], a);
        part[pr][qq][m] = a;
    }
    __syncthreads();
    if (tid < 2 * MD) {
        int pr = tid / MD, m = tid % MD;
        float a = b3[m] + part[pr][0][m] + part[pr][1][m]
                        + part[pr][2][m] + part[pr][3][m];
        float sp = fmaxf(a, 0.f) + log1pf(expf(-fabsf(a)));  // jax softplus
        g_tab[(p0 + pr) * MD + m] = sp;
    }
}

// ---------------------------------------------------------------------------
// Per-pair energy: table lookup + anchored RBF product chain + smoothstep.
// ---------------------------------------------------------------------------
__device__ __forceinline__ float pair_energy(float d2, int jj,
                                             const int* __restrict__ seqb,
                                             int aa_base)
{
    float r = sqrtf(d2);
    int aj = __ldg(seqb + jj);
    const float* tp = g_tab + (aa_base + aj) * MD;
    const float C2  = 0.13533528323661270f;      // e^-2
    const float C6  = 2.4787521766663585e-3f;    // e^-6
    const float C10 = 4.5399929762484854e-5f;    // e^-10
    float t  = r - 8.f;
    float p3 = __expf(-2.f * t * t);
    float G  = __expf( 4.f * t);
    float Gi = __expf(-4.f * t);
    float p4 = p3 * G  * C2;
    float p5 = p4 * G  * C6;
    float p6 = p5 * G  * C10;
    float p2 = p3 * Gi * C2;
    float p1 = p2 * Gi * C6;
    float p0 = p1 * Gi * C10;
    float att = tp[0] * p0 + tp[1] * p1 + tp[2] * p2 + tp[3] * p3
              + tp[4] * p4 + tp[5] * p5 + tp[6] * p6;
    float tt = fminf(fmaxf((r - 10.f) * 0.5f, 0.f), 1.f);
    float sw = 1.f - tt * tt * (3.f - 2.f * tt);
    return -att * sw;
}

// ---------------------------------------------------------------------------
// Kernel 1: one row per CTA (R7 structure, proven). SoA float2 loads +
// f32x2 packed distance math in the scan; everything downstream identical
// to the passing R7 kernel. key = (bits(d2) << 11) | j.
// ---------------------------------------------------------------------------
__global__ void __launch_bounds__(256) topk_energy_kernel(const int* __restrict__ seq)
{
    __shared__ unsigned long long seg[8 * 256];    // 16 KB
    __shared__ unsigned long long buf[BCAP];       // 2 KB
    __shared__ int hist[256];
    __shared__ int s_cnt[8];
    __shared__ int wtot[8];
    __shared__ float wsum[8];
    __shared__ int s_B, s_targ, s_bcnt;
    __shared__ unsigned long long s_T;
    __shared__ unsigned long long s_pref;

    const int tid = threadIdx.x;
    const int w = tid >> 5, lane = tid & 31;
    const unsigned lanelt = (1u << lane) - 1u;
    const int row = blockIdx.x;
    const int b = row >> 11;
    const int i = row & (Ln - 1);
    const float* __restrict__ Rx = g_Rx + b * Ln;
    const float* __restrict__ Ry = g_Ry + b * Ln;
    const float* __restrict__ Rz = g_Rz + b * Ln;
    const int* __restrict__ seqb = seq + b * Ln;

    const float xi = __ldg(Rx + i), yi = __ldg(Ry + i), zi = __ldg(Rz + i);

    if (tid == 0) { s_bcnt = 0; s_T = ~0ull; }

    unsigned long long nxi, nyi, nzi, peps;
    {
        float mx = -xi, my = -yi, mz = -zi;
        PACK2(nxi, mx, mx); PACK2(nyi, my, my); PACK2(nzi, mz, mz);
        PACK2(peps, 1e-12f, 1e-12f);
    }

    // --- Scan: warp w owns j in [256w, 256w+256); 2 j's/lane/iter via
    //     float2 SoA loads + f32x2 packed math; ballot compaction. ---
    int cnt = 0;
    #pragma unroll
    for (int it = 0; it < 4; it++) {
        const int j0 = (w << 8) + (it << 6) + 2 * lane;
        const int vv = (w << 7) + (it << 5) + lane;
        float2 xv = __ldg((const float2*)Rx + vv);
        float2 yv = __ldg((const float2*)Ry + vv);
        float2 zv = __ldg((const float2*)Rz + vv);
        unsigned long long px, py, pz, d2p;
        PACK2(px, xv.x, xv.y); PACK2(py, yv.x, yv.y); PACK2(pz, zv.x, zv.y);
        ADD2(px, px, nxi); ADD2(py, py, nyi); ADD2(pz, pz, nzi);
        FMA2(d2p, pz, pz, peps);
        FMA2(d2p, py, py, d2p);
        FMA2(d2p, px, px, d2p);
        float d2lo, d2hi;
        UNPACK2(d2lo, d2hi, d2p);

        bool p0 = (d2lo < D2CUT) && ((unsigned)(j0 - i + EXCL) > 2u * EXCL);
        unsigned m0 = __ballot_sync(0xffffffffu, p0);
        if (p0) {
            seg[(w << 8) + cnt + __popc(m0 & lanelt)] =
                (((unsigned long long)__float_as_uint(d2lo)) << 11) | (unsigned)j0;
        }
        cnt += __popc(m0);

        bool p1 = (d2hi < D2CUT) && ((unsigned)(j0 + 1 - i + EXCL) > 2u * EXCL);
        unsigned m1 = __ballot_sync(0xffffffffu, p1);
        if (p1) {
            seg[(w << 8) + cnt + __popc(m1 & lanelt)] =
                (((unsigned long long)__float_as_uint(d2hi)) << 11) | (unsigned)(j0 + 1);
        }
        cnt += __popc(m1);
    }
    if (lane == 0) s_cnt[w] = cnt;
    __syncthreads();

    int ctot = 0;
    #pragma unroll
    for (int s = 0; s < 8; s++) ctot += s_cnt[s];

    if (ctot > KSEL) {
        // --- 1-pass 256-bin linear-d2 histogram (separate pass, as in R7) ---
        hist[tid] = 0;
        __syncthreads();
        #pragma unroll 1
        for (int s = 0; s < 8; s++) {
            const int cs = s_cnt[s];
            for (int c = tid; c < cs; c += 256) {
                float d2 = __uint_as_float((unsigned)(seg[(s << 8) + c] >> 11));
                int bin = min((int)(d2 * BINSCALE), 255);
                atomicAdd(&hist[bin], 1);
            }
        }
        __syncthreads();

        // --- Block inclusive scan over 256 bins, find crossing bin ---
        int v = hist[tid];
        int incl = v;
        #pragma unroll
        for (int o = 1; o < 32; o <<= 1) {
            int t = __shfl_up_sync(0xffffffffu, incl, o);
            if (lane >= o) incl += t;
        }
        if (lane == 31) wtot[w] = incl;
        __syncthreads();
        if (tid == 0) {
            int r = 0;
            #pragma unroll
            for (int q = 0; q < 8; q++) { int t = wtot[q]; wtot[q] = r; r += t; }
        }
        __syncthreads();
        incl += wtot[w];
        int excl = incl - v;
        if (excl < KSEL && KSEL <= incl) { s_B = tid; s_targ = KSEL - excl; }
        __syncthreads();
        const int B = s_B;

        // --- Gather the crossing bucket ---
        #pragma unroll 1
        for (int s = 0; s < 8; s++) {
            const int cs = s_cnt[s];
            for (int c = tid; c < cs; c += 256) {
                unsigned long long key = seg[(s << 8) + c];
                float d2 = __uint_as_float((unsigned)(key >> 11));
                int bin = min((int)(d2 * BINSCALE), 255);
                if (bin == B) {
                    int pos = atomicAdd(&s_bcnt, 1);
                    if (pos < BCAP) buf[pos] = key;
                }
            }
        }
        __syncthreads();
        const int bc = s_bcnt;

        if (bc <= BCAP) {
            // --- Exact threshold by warp-0 rank count (unique 43-bit keys) ---
            if (tid < 32) {
                const int tg = s_targ;
                for (int c = lane; c < bc; c += 32) {
                    unsigned long long key = buf[c];
                    int rank = 0;
                    for (int t = 0; t < bc; t++) rank += (buf[t] < key);
                    if (rank == tg - 1) s_T = key;
                }
            }
            __syncthreads();
        } else {
            // --- Fallback (never expected): exact 6x8-bit radix over segments ---
            if (tid == 0) { s_pref = 0ull; s_targ = KSEL; }
            __syncthreads();
            for (int pass = 0; pass < 6; pass++) {
                const int shift = 40 - 8 * pass;
                hist[tid] = 0;
                __syncthreads();
                const unsigned long long hp = s_pref >> (shift + 8);
                for (int s = 0; s < 8; s++) {
                    const int cs = s_cnt[s];
                    for (int c = tid; c < cs; c += 256) {
                        unsigned long long key = seg[(s << 8) + c];
                        if ((key >> (shift + 8)) == hp)
                            atomicAdd(&hist[(int)((key >> shift) & 255)], 1);
                    }
                }
                __syncthreads();
                if (tid < 32) {
                    const int base = tid * 8;
                    int c8[8]; int ssum = 0;
                    #pragma unroll
                    for (int t = 0; t < 8; t++) { c8[t] = hist[base + t]; ssum += c8[t]; }
                    int incl2 = ssum;
                    #pragma unroll
                    for (int o = 1; o < 32; o <<= 1) {
                        int t = __shfl_up_sync(0xffffffffu, incl2, o);
                        if (tid >= o) incl2 += t;
                    }
                    int excl2 = incl2 - ssum;
                    const int tgt = s_targ;
                    const unsigned long long pref = s_pref;
                    __syncwarp();
                    int run = excl2;
                    #pragma unroll
                    for (int t = 0; t < 8; t++) {
                        if (run < tgt && tgt <= run + c8[t]) {
                            s_pref = pref | ((unsigned long long)(base + t) << shift);
                            s_targ = tgt - run;
                        }
                        run += c8[t];
                    }
                }
                __syncthreads();
            }
            if (tid == 0) s_T = s_pref;
            __syncthreads();
        }
    }

    // --- Energy over selected candidates (segment-major, as in R7) ---
    const unsigned long long T = s_T;      // ~0 when ctot <= KSEL
    const int aa_base = __ldg(seqb + i) * NAA;
    float local = 0.f;
    #pragma unroll 1
    for (int s = 0; s < 8; s++) {
        const int cs = s_cnt[s];
        for (int c = tid; c < cs; c += 256) {
            unsigned long long key = seg[(s << 8) + c];
            if (key <= T) {
                float d2 = __uint_as_float((unsigned)(key >> 11));
                local += pair_energy(d2, (int)(key & 2047ull), seqb, aa_base);
            }
        }
    }

    // --- Deterministic block reduction ---
    #pragma unroll
    for (int o = 16; o > 0; o >>= 1)
        local += __shfl_down_sync(0xffffffffu, local, o);
    if (lane == 0) wsum[w] = local;
    __syncthreads();
    if (tid == 0) {
        float s = 0.f;
        #pragma unroll
        for (int q = 0; q < 8; q++) s += wsum[q];
        g_rowsum[row] = s;
    }
}

// ---------------------------------------------------------------------------
// Kernel 2: deterministic per-batch reduction (1024 threads)
// ---------------------------------------------------------------------------
__global__ void __launch_bounds__(1024) reduce_kernel(float* __restrict__ out)
{
    __shared__ float s[1024];
    const int b = blockIdx.x;
    const int tid = threadIdx.x;
    s[tid] = g_rowsum[b * Ln + tid] + g_rowsum[b * Ln + 1024 + tid];
    __syncthreads();
    for (int o = 512; o > 0; o >>= 1) {
        if (tid < o) s[tid] += s[tid + o];
        __syncthreads();
    }
    if (tid == 0) out[b] = s[0];
}

// ---------------------------------------------------------------------------
extern "C" void kernel_launch(void* const* d_in, const int* in_sizes, int n_in,
                              void* d_out, int out_size)
{
    const float* R       = (const float*)d_in[0];
    const int*   seq     = (const int*)  d_in[1];
    const float* emb     = (const float*)d_in[2];
    const float* W1      = (const float*)d_in[3];
    const float* b1      = (const float*)d_in[4];
    const float* W2      = (const float*)d_in[5];
    const float* b2      = (const float*)d_in[6];
    const float* W3      = (const float*)d_in[7];
    const float* b3      = (const float*)d_in[8];
    float* out = (float*)d_out;

    transpose_kernel<<<(Bn * Ln) / 256, 256>>>(R);
    table_kernel<<<NAA * NAA / 2, 512>>>(emb, W1, b1, W2, b2, W3, b3);
    topk_energy_kernel<<<Bn * Ln, 256>>>(seq);
    reduce_kernel<<<Bn, 1024>>>(out);
}

// round 10
// speedup vs baseline: 1.0685x; 1.0685x over previous
#include <cuda_runtime.h>
#include <cuda_bf16.h>
#include <math.h>

#define Bn    8
#define Ln    2048
#define KSEL  64
#define EXCL  3
#define NAA   20
#define EMB   16
#define MD    7
#define D2CUT 144.0f      // r >= 12 -> smoothstep == 0 -> zero energy
#define BCAP  256         // bucket capacity before radix fallback
#define BINSCALE (256.0f / 144.0f)

// Scratch (device globals: no allocation allowed)
__device__ float4 g_R4[Bn * Ln];              // padded SoA->AoS16 coords
__device__ float g_rowsum[Bn * Ln];
__device__ float g_tab[NAA * NAA * MD];       // softplus(MLP(aa_i,aa_j))

// ---------------------------------------------------------------------------
// Kernel T: pad R (stride 3) into float4 (stride 4) for 1-LDG.128-per-j scans
// ---------------------------------------------------------------------------
__global__ void __launch_bounds__(256) pad_kernel(const float* __restrict__ R)
{
    int p = blockIdx.x * 256 + threadIdx.x;
    float x = R[3 * p + 0];
    float y = R[3 * p + 1];
    float z = R[3 * p + 2];
    g_R4[p] = make_float4(x, y, z, 0.f);
}

// ---------------------------------------------------------------------------
// Kernel 0: exact fp32 MLP over 400 AA pairs -> 400x7 table.
// 2 pairs/block (ILP-2), 512 threads, 4-way K-split (short serial chains).
// ---------------------------------------------------------------------------
__global__ void __launch_bounds__(512) table_kernel(
    const float* __restrict__ emb,
    const float* __restrict__ W1, const float* __restrict__ b1,
    const float* __restrict__ W2, const float* __restrict__ b2,
    const float* __restrict__ W3, const float* __restrict__ b3)
{
    __shared__ float x[2][48];
    __shared__ float h1[2][128];
    __shared__ float h2[2][128];
    __shared__ float part[2][4][128];

    const int p0 = blockIdx.x * 2;
    const int tid = threadIdx.x;
    const int n = tid & 127;
    const int q4 = tid >> 7;            // 0..3

    if (tid < 2 * EMB) {
        int pr = tid >> 4, c = tid & 15;
        int p = p0 + pr;
        float ei = emb[(p / NAA) * EMB + c];
        float ej = emb[(p % NAA) * EMB + c];
        x[pr][c] = ei; x[pr][EMB + c] = ej; x[pr][2 * EMB + c] = ei * ej;
    }
    __syncthreads();

    {   // Layer 1: K=48, 4 x 12
        float a0 = 0.f, a1 = 0.f;
        const int k0 = q4 * 12;
        #pragma unroll
        for (int k = 0; k < 12; k++) {
            float w = W1[(k0 + k) * 128 + n];
            a0 = fmaf(x[0][k0 + k], w, a0);
            a1 = fmaf(x[1][k0 + k], w, a1);
        }
        part[0][q4][n] = a0; part[1][q4][n] = a1;
    }
    __syncthreads();
    if (q4 < 2)
        h1[q4][n] = fmaxf(b1[n] + part[q4][0][n] + part[q4][1][n]
                                + part[q4][2][n] + part[q4][3][n], 0.f);
    __syncthreads();

    {   // Layer 2: K=128, 4 x 32
        float a0 = 0.f, a1 = 0.f;
        const int k0 = q4 * 32;
        #pragma unroll
        for (int k = 0; k < 32; k++) {
            float w = W2[(k0 + k) * 128 + n];
            a0 = fmaf(h1[0][k0 + k], w, a0);
            a1 = fmaf(h1[1][k0 + k], w, a1);
        }
        part[0][q4][n] = a0; part[1][q4][n] = a1;
    }
    __syncthreads();
    if (q4 < 2)
        h2[q4][n] = fmaxf(b2[n] + part[q4][0][n] + part[q4][1][n]
                                + part[q4][2][n] + part[q4][3][n], 0.f);
    __syncthreads();

    if (tid < 2 * MD * 4) {   // Layer 3: K=128, 4 x 32, 7 outs x 2 pairs
        int pr = tid / 28, rem = tid % 28;
        int m = rem % MD, qq = rem / MD;
        float a = 0.f;
        const int k0 = qq * 32;
        #pragma unroll
        for (int k = 0; k < 32; k++)
            a = fmaf(h2[pr][k0 + k], W3[(k0 + k) * MD + m], a);
        part[pr][qq][m] = a;
    }
    __syncthreads();
    if (tid < 2 * MD) {
        int pr = tid / MD, m = tid % MD;
        float a = b3[m] + part[pr][0][m] + part[pr][1][m]
                        + part[pr][2][m] + part[pr][3][m];
        float sp = fmaxf(a, 0.f) + log1pf(expf(-fabsf(a)));  // jax softplus
        g_tab[(p0 + pr) * MD + m] = sp;
    }
}

// ---------------------------------------------------------------------------
// Per-pair energy: table lookup + anchored RBF product chain + smoothstep.
// ---------------------------------------------------------------------------
__device__ __forceinline__ float pair_energy(float d2, int jj,
                                             const int* __restrict__ seqb,
                                             int aa_base)
{
    float r = d2 * rsqrtf(d2);               // d2 >= 1e-12: safe, 1 MUFU
    int aj = __ldg(seqb + jj);
    const float* tp = g_tab + (aa_base + aj) * MD;
    const float C2  = 0.13533528323661270f;      // e^-2
    const float C6  = 2.4787521766663585e-3f;    // e^-6
    const float C10 = 4.5399929762484854e-5f;    // e^-10
    float t  = r - 8.f;
    float p3 = __expf(-2.f * t * t);
    float G  = __expf( 4.f * t);
    float Gi = __expf(-4.f * t);
    float p4 = p3 * G  * C2;
    float p5 = p4 * G  * C6;
    float p6 = p5 * G  * C10;
    float p2 = p3 * Gi * C2;
    float p1 = p2 * Gi * C6;
    float p0 = p1 * Gi * C10;
    float att = tp[0] * p0 + tp[1] * p1 + tp[2] * p2 + tp[3] * p3
              + tp[4] * p4 + tp[5] * p5 + tp[6] * p6;
    float tt = fminf(fmaxf((r - 10.f) * 0.5f, 0.f), 1.f);
    float sw = 1.f - tt * tt * (3.f - 2.f * tt);
    return -att * sw;
}

// ---------------------------------------------------------------------------
// Kernel 1: one row per CTA (R7 structure, proven). float4 coordinate loads;
// warp-segmented ballot compaction, 1-pass 256-bin linear-d2 histogram
// select, tiny-bucket exact rank-count, radix fallback.
// key = (bits(d2) << 11) | j  (43 bits, unique).
// ---------------------------------------------------------------------------
__global__ void __launch_bounds__(256) topk_energy_kernel(const int* __restrict__ seq)
{
    __shared__ unsigned long long seg[8 * 256];    // 16 KB
    __shared__ unsigned long long buf[BCAP];       // 2 KB
    __shared__ int hist[256];
    __shared__ int s_cnt[8];
    __shared__ int wtot[8];
    __shared__ float wsum[8];
    __shared__ int s_B, s_targ, s_bcnt;
    __shared__ unsigned long long s_T;
    __shared__ unsigned long long s_pref;

    const int tid = threadIdx.x;
    const int w = tid >> 5, lane = tid & 31;
    const unsigned lanelt = (1u << lane) - 1u;
    const int row = blockIdx.x;
    const int b = row >> 11;
    const int i = row & (Ln - 1);
    const float4* __restrict__ R4b = g_R4 + b * Ln;
    const int* __restrict__ seqb = seq + b * Ln;

    const float4 ri = __ldg(R4b + i);
    const float xi = ri.x, yi = ri.y, zi = ri.z;

    if (tid == 0) { s_bcnt = 0; s_T = ~0ull; }

    // --- Scan: warp w owns j in [256w, 256w+256); 1 LDG.128 per j ---
    int cnt = 0;
    #pragma unroll
    for (int it = 0; it < 8; it++) {
        const int j = (w << 8) + (it << 5) + lane;
        float4 rj = __ldg(R4b + j);
        float dx = xi - rj.x;
        float dy = yi - rj.y;
        float dz = zi - rj.z;
        float d2 = fmaf(dx, dx, fmaf(dy, dy, fmaf(dz, dz, 1e-12f)));
        bool p = (d2 < D2CUT) && ((unsigned)(j - i + EXCL) > 2u * EXCL);
        unsigned m = __ballot_sync(0xffffffffu, p);
        if (p) {
            seg[(w << 8) + cnt + __popc(m & lanelt)] =
                (((unsigned long long)__float_as_uint(d2)) << 11) | (unsigned)j;
        }
        cnt += __popc(m);
    }
    if (lane == 0) s_cnt[w] = cnt;
    __syncthreads();

    int ctot = 0;
    #pragma unroll
    for (int s = 0; s < 8; s++) ctot += s_cnt[s];

    if (ctot > KSEL) {
        // --- 1-pass 256-bin linear-d2 histogram ---
        hist[tid] = 0;
        __syncthreads();
        #pragma unroll 1
        for (int s = 0; s < 8; s++) {
            const int cs = s_cnt[s];
            for (int c = tid; c < cs; c += 256) {
                float d2 = __uint_as_float((unsigned)(seg[(s << 8) + c] >> 11));
                int bin = min((int)(d2 * BINSCALE), 255);
                atomicAdd(&hist[bin], 1);
            }
        }
        __syncthreads();

        // --- Block inclusive scan over 256 bins, find crossing bin ---
        int v = hist[tid];
        int incl = v;
        #pragma unroll
        for (int o = 1; o < 32; o <<= 1) {
            int t = __shfl_up_sync(0xffffffffu, incl, o);
            if (lane >= o) incl += t;
        }
        if (lane == 31) wtot[w] = incl;
        __syncthreads();
        if (tid == 0) {
            int r = 0;
            #pragma unroll
            for (int q = 0; q < 8; q++) { int t = wtot[q]; wtot[q] = r; r += t; }
        }
        __syncthreads();
        incl += wtot[w];
        int excl = incl - v;
        if (excl < KSEL && KSEL <= incl) { s_B = tid; s_targ = KSEL - excl; }
        __syncthreads();
        const int B = s_B;

        // --- Gather the crossing bucket ---
        #pragma unroll 1
        for (int s = 0; s < 8; s++) {
            const int cs = s_cnt[s];
            for (int c = tid; c < cs; c += 256) {
                unsigned long long key = seg[(s << 8) + c];
                float d2 = __uint_as_float((unsigned)(key >> 11));
                int bin = min((int)(d2 * BINSCALE), 255);
                if (bin == B) {
                    int pos = atomicAdd(&s_bcnt, 1);
                    if (pos < BCAP) buf[pos] = key;
                }
            }
        }
        __syncthreads();
        const int bc = s_bcnt;

        if (bc <= BCAP) {
            // --- Exact threshold by warp-0 rank count (unique 43-bit keys) ---
            if (tid < 32) {
                const int tg = s_targ;
                for (int c = lane; c < bc; c += 32) {
                    unsigned long long key = buf[c];
                    int rank = 0;
                    for (int t = 0; t < bc; t++) rank += (buf[t] < key);
                    if (rank == tg - 1) s_T = key;
                }
            }
            __syncthreads();
        } else {
            // --- Fallback (never expected): exact 6x8-bit radix over segments ---
            if (tid == 0) { s_pref = 0ull; s_targ = KSEL; }
            __syncthreads();
            for (int pass = 0; pass < 6; pass++) {
                const int shift = 40 - 8 * pass;
                hist[tid] = 0;
                __syncthreads();
                const unsigned long long hp = s_pref >> (shift + 8);
                for (int s = 0; s < 8; s++) {
                    const int cs = s_cnt[s];
                    for (int c = tid; c < cs; c += 256) {
                        unsigned long long key = seg[(s << 8) + c];
                        if ((key >> (shift + 8)) == hp)
                            atomicAdd(&hist[(int)((key >> shift) & 255)], 1);
                    }
                }
                __syncthreads();
                if (tid < 32) {
                    const int base = tid * 8;
                    int c8[8]; int ssum = 0;
                    #pragma unroll
                    for (int t = 0; t < 8; t++) { c8[t] = hist[base + t]; ssum += c8[t]; }
                    int incl2 = ssum;
                    #pragma unroll
                    for (int o = 1; o < 32; o <<= 1) {
                        int t = __shfl_up_sync(0xffffffffu, incl2, o);
                        if (tid >= o) incl2 += t;
                    }
                    int excl2 = incl2 - ssum;
                    const int tgt = s_targ;
                    const unsigned long long pref = s_pref;
                    __syncwarp();
                    int run = excl2;
                    #pragma unroll
                    for (int t = 0; t < 8; t++) {
                        if (run < tgt && tgt <= run + c8[t]) {
                            s_pref = pref | ((unsigned long long)(base + t) << shift);
                            s_targ = tgt - run;
                        }
                        run += c8[t];
                    }
                }
                __syncthreads();
            }
            if (tid == 0) s_T = s_pref;
            __syncthreads();
        }
    }

    // --- Energy over selected candidates (segment-major) ---
    const unsigned long long T = s_T;      // ~0 when ctot <= KSEL
    const int aa_base = __ldg(seqb + i) * NAA;
    float local = 0.f;
    #pragma unroll 1
    for (int s = 0; s < 8; s++) {
        const int cs = s_cnt[s];
        for (int c = tid; c < cs; c += 256) {
            unsigned long long key = seg[(s << 8) + c];
            if (key <= T) {
                float d2 = __uint_as_float((unsigned)(key >> 11));
                local += pair_energy(d2, (int)(key & 2047ull), seqb, aa_base);
            }
        }
    }

    // --- Deterministic block reduction ---
    #pragma unroll
    for (int o = 16; o > 0; o >>= 1)
        local += __shfl_down_sync(0xffffffffu, local, o);
    if (lane == 0) wsum[w] = local;
    __syncthreads();
    if (tid == 0) {
        float s = 0.f;
        #pragma unroll
        for (int q = 0; q < 8; q++) s += wsum[q];
        g_rowsum[row] = s;
    }
}

// ---------------------------------------------------------------------------
// Kernel 2: deterministic per-batch reduction
// ---------------------------------------------------------------------------
__global__ void __launch_bounds__(256) reduce_kernel(float* __restrict__ out)
{
    __shared__ float s[256];
    const int b = blockIdx.x;
    const int tid = threadIdx.x;
    float v = 0.f;
    for (int i = tid; i < Ln; i += 256) v += g_rowsum[b * Ln + i];
    s[tid] = v;
    __syncthreads();
    for (int o = 128; o > 0; o >>= 1) {
        if (tid < o) s[tid] += s[tid + o];
        __syncthreads();
    }
    if (tid == 0) out[b] = s[0];
}

// ---------------------------------------------------------------------------
extern "C" void kernel_launch(void* const* d_in, const int* in_sizes, int n_in,
                              void* d_out, int out_size)
{
    const float* R       = (const float*)d_in[0];
    const int*   seq     = (const int*)  d_in[1];
    const float* emb     = (const float*)d_in[2];
    const float* W1      = (const float*)d_in[3];
    const float* b1      = (const float*)d_in[4];
    const float* W2      = (const float*)d_in[5];
    const float* b2      = (const float*)d_in[6];
    const float* W3      = (const float*)d_in[7];
    const float* b3      = (const float*)d_in[8];
    float* out = (float*)d_out;

    pad_kernel<<<(Bn * Ln) / 256, 256>>>(R);
    table_kernel<<<NAA * NAA / 2, 512>>>(emb, W1, b1, W2, b2, W3, b3);
    topk_energy_kernel<<<Bn * Ln, 256>>>(seq);
    reduce_kernel<<<Bn, 256>>>(out);
}

// round 11
// speedup vs baseline: 1.1298x; 1.0573x over previous
#include <cuda_runtime.h>
#include <cuda_bf16.h>
#include <math.h>

#define Bn    8
#define Ln    2048
#define KSEL  64
#define EXCL  3
#define NAA   20
#define EMB   16
#define MD    7
#define D2CUT 144.0f      // r >= 12 -> smoothstep == 0 -> zero energy
#define BCAP  256         // bucket capacity before radix fallback
#define CANDN 1024        // flat candidate buffer (E[max] ~620, 19 sigma)
#define BINSCALE (256.0f / 144.0f)

// Scratch (device globals: no allocation allowed)
__device__ float g_rowsum[Bn * Ln];
__device__ float g_tab[NAA * NAA * MD];       // softplus(MLP(aa_i,aa_j))

// ---------------------------------------------------------------------------
// Kernel 0: exact fp32 MLP over 400 AA pairs -> 400x7 table.
// 2 pairs/block (ILP-2), 512 threads, 4-way K-split (short serial chains).
// ---------------------------------------------------------------------------
__global__ void __launch_bounds__(512) table_kernel(
    const float* __restrict__ emb,
    const float* __restrict__ W1, const float* __restrict__ b1,
    const float* __restrict__ W2, const float* __restrict__ b2,
    const float* __restrict__ W3, const float* __restrict__ b3)
{
    __shared__ float x[2][48];
    __shared__ float h1[2][128];
    __shared__ float h2[2][128];
    __shared__ float part[2][4][128];

    const int p0 = blockIdx.x * 2;
    const int tid = threadIdx.x;
    const int n = tid & 127;
    const int q4 = tid >> 7;            // 0..3

    if (tid < 2 * EMB) {
        int pr = tid >> 4, c = tid & 15;
        int p = p0 + pr;
        float ei = emb[(p / NAA) * EMB + c];
        float ej = emb[(p % NAA) * EMB + c];
        x[pr][c] = ei; x[pr][EMB + c] = ej; x[pr][2 * EMB + c] = ei * ej;
    }
    __syncthreads();

    {   // Layer 1: K=48, 4 x 12
        float a0 = 0.f, a1 = 0.f;
        const int k0 = q4 * 12;
        #pragma unroll
        for (int k = 0; k < 12; k++) {
            float w = W1[(k0 + k) * 128 + n];
            a0 = fmaf(x[0][k0 + k], w, a0);
            a1 = fmaf(x[1][k0 + k], w, a1);
        }
        part[0][q4][n] = a0; part[1][q4][n] = a1;
    }
    __syncthreads();
    if (q4 < 2)
        h1[q4][n] = fmaxf(b1[n] + part[q4][0][n] + part[q4][1][n]
                                + part[q4][2][n] + part[q4][3][n], 0.f);
    __syncthreads();

    {   // Layer 2: K=128, 4 x 32
        float a0 = 0.f, a1 = 0.f;
        const int k0 = q4 * 32;
        #pragma unroll
        for (int k = 0; k < 32; k++) {
            float w = W2[(k0 + k) * 128 + n];
            a0 = fmaf(h1[0][k0 + k], w, a0);
            a1 = fmaf(h1[1][k0 + k], w, a1);
        }
        part[0][q4][n] = a0; part[1][q4][n] = a1;
    }
    __syncthreads();
    if (q4 < 2)
        h2[q4][n] = fmaxf(b2[n] + part[q4][0][n] + part[q4][1][n]
                                + part[q4][2][n] + part[q4][3][n], 0.f);
    __syncthreads();

    if (tid < 2 * MD * 4) {   // Layer 3: K=128, 4 x 32, 7 outs x 2 pairs
        int pr = tid / 28, rem = tid % 28;
        int m = rem % MD, qq = rem / MD;
        float a = 0.f;
        const int k0 = qq * 32;
        #pragma unroll
        for (int k = 0; k < 32; k++)
            a = fmaf(h2[pr][k0 + k], W3[(k0 + k) * MD + m], a);
        part[pr][qq][m] = a;
    }
    __syncthreads();
    if (tid < 2 * MD) {
        int pr = tid / MD, m = tid % MD;
        float a = b3[m] + part[pr][0][m] + part[pr][1][m]
                        + part[pr][2][m] + part[pr][3][m];
        float sp = fmaxf(a, 0.f) + log1pf(expf(-fabsf(a)));  // jax softplus
        g_tab[(p0 + pr) * MD + m] = sp;
    }
}

// ---------------------------------------------------------------------------
// Per-pair energy: table lookup + anchored RBF product chain + smoothstep.
// ---------------------------------------------------------------------------
__device__ __forceinline__ float pair_energy(float d2, int jj,
                                             const int* __restrict__ seqb,
                                             int aa_base)
{
    float r = d2 * rsqrtf(d2);               // d2 >= 1e-12: safe, 1 MUFU
    int aj = __ldg(seqb + jj);
    const float* tp = g_tab + (aa_base + aj) * MD;
    const float C2  = 0.13533528323661270f;      // e^-2
    const float C6  = 2.4787521766663585e-3f;    // e^-6
    const float C10 = 4.5399929762484854e-5f;    // e^-10
    float t  = r - 8.f;
    float p3 = __expf(-2.f * t * t);
    float G  = __expf( 4.f * t);
    float Gi = __expf(-4.f * t);
    float p4 = p3 * G  * C2;
    float p5 = p4 * G  * C6;
    float p6 = p5 * G  * C10;
    float p2 = p3 * Gi * C2;
    float p1 = p2 * Gi * C6;
    float p0 = p1 * Gi * C10;
    float att = tp[0] * p0 + tp[1] * p1 + tp[2] * p2 + tp[3] * p3
              + tp[4] * p4 + tp[5] * p5 + tp[6] * p6;
    float tt = fminf(fmaxf((r - 10.f) * 0.5f, 0.f), 1.f);
    float sw = 1.f - tt * tt * (3.f - 2.f * tt);
    return -att * sw;
}

// ---------------------------------------------------------------------------
// Kernel 1: one row per CTA. R7 scan (proven) + flat-compacted select:
// segments -> cand[CANDN], then histogram/gather/energy are single rounds.
// Below-bucket energy fused into the gather pass (bin < B => key < T).
// key = (bits(d2) << 11) | j  (43 bits, unique). Exact fallbacks retained.
// ---------------------------------------------------------------------------
__global__ void __launch_bounds__(256) topk_energy_kernel(
    const float* __restrict__ R, const int* __restrict__ seq)
{
    __shared__ unsigned long long seg[8 * 256];    // 16 KB
    __shared__ unsigned long long cand[CANDN];     // 8 KB
    __shared__ unsigned long long buf[BCAP];       // 2 KB
    __shared__ int hist[256];
    __shared__ int s_cnt[8];
    __shared__ int wtot[8];
    __shared__ float wsum[8];
    __shared__ int s_B, s_targ, s_bcnt;
    __shared__ unsigned long long s_T;
    __shared__ unsigned long long s_pref;

    const int tid = threadIdx.x;
    const int w = tid >> 5, lane = tid & 31;
    const unsigned lanelt = (1u << lane) - 1u;
    const int row = blockIdx.x;
    const int b = row >> 11;
    const int i = row & (Ln - 1);
    const float* __restrict__ Rb = R + (size_t)b * Ln * 3;
    const int* __restrict__ seqb = seq + b * Ln;

    const float xi = Rb[3 * i], yi = Rb[3 * i + 1], zi = Rb[3 * i + 2];

    if (tid == 0) { s_bcnt = 0; s_T = ~0ull; }

    // --- Scan: warp w owns j in [256w, 256w+256), ballot compaction ---
    int cnt = 0;
    #pragma unroll
    for (int it = 0; it < 8; it++) {
        const int j = (w << 8) + (it << 5) + lane;
        float dx = xi - Rb[3 * j];
        float dy = yi - Rb[3 * j + 1];
        float dz = zi - Rb[3 * j + 2];
        float d2 = fmaf(dx, dx, fmaf(dy, dy, fmaf(dz, dz, 1e-12f)));
        bool p = (d2 < D2CUT) && ((unsigned)(j - i + EXCL) > 2u * EXCL);
        unsigned m = __ballot_sync(0xffffffffu, p);
        if (p) {
            seg[(w << 8) + cnt + __popc(m & lanelt)] =
                (((unsigned long long)__float_as_uint(d2)) << 11) | (unsigned)j;
        }
        cnt += __popc(m);
    }
    if (lane == 0) s_cnt[w] = cnt;
    __syncthreads();

    int ctot = 0;
    #pragma unroll
    for (int s = 0; s < 8; s++) ctot += s_cnt[s];

    const int aa_base = __ldg(seqb + i) * NAA;
    float local = 0.f;

    if (ctot <= CANDN) {
        // ===================== FLAT FAST PATH =====================
        // Compact segments into cand (cs <= 256 = blockDim: 1 stmt each)
        {
            int off = 0;
            #pragma unroll
            for (int s = 0; s < 8; s++) {
                int cs = s_cnt[s];
                if (tid < cs) cand[off + tid] = seg[(s << 8) + tid];
                off += cs;
            }
        }
        hist[tid] = 0;
        __syncthreads();

        if (ctot > KSEL) {
            // --- 1-round 256-bin linear-d2 histogram ---
            for (int g = tid; g < ctot; g += 256) {
                float d2 = __uint_as_float((unsigned)(cand[g] >> 11));
                atomicAdd(&hist[min((int)(d2 * BINSCALE), 255)], 1);
            }
            __syncthreads();

            // --- Block inclusive scan over bins, find crossing bin ---
            int v = hist[tid];
            int incl = v;
            #pragma unroll
            for (int o = 1; o < 32; o <<= 1) {
                int t = __shfl_up_sync(0xffffffffu, incl, o);
                if (lane >= o) incl += t;
            }
            if (lane == 31) wtot[w] = incl;
            __syncthreads();
            if (tid == 0) {
                int r = 0;
                #pragma unroll
                for (int q = 0; q < 8; q++) { int t = wtot[q]; wtot[q] = r; r += t; }
            }
            __syncthreads();
            incl += wtot[w];
            int excl = incl - v;
            if (excl < KSEL && KSEL <= incl) { s_B = tid; s_targ = KSEL - excl; }
            __syncthreads();
            const int B = s_B;

            // --- Gather bucket + fused below-bucket energy (bin<B => selected) ---
            for (int g = tid; g < ctot; g += 256) {
                unsigned long long key = cand[g];
                float d2 = __uint_as_float((unsigned)(key >> 11));
                int bin = min((int)(d2 * BINSCALE), 255);
                if (bin < B) {
                    local += pair_energy(d2, (int)(key & 2047ull), seqb, aa_base);
                } else if (bin == B) {
                    int pos = atomicAdd(&s_bcnt, 1);
                    if (pos < BCAP) buf[pos] = key;
                }
            }
            __syncthreads();
            const int bc = s_bcnt;

            if (bc <= BCAP) {
                // --- Exact threshold by warp-0 rank count (unique keys) ---
                if (tid < 32) {
                    const int tg = s_targ;
                    for (int c = lane; c < bc; c += 32) {
                        unsigned long long key = buf[c];
                        int rank = 0;
                        for (int t = 0; t < bc; t++) rank += (buf[t] < key);
                        if (rank == tg - 1) s_T = key;
                    }
                }
                __syncthreads();
                const unsigned long long T = s_T;
                for (int g = tid; g < bc; g += 256) {
                    unsigned long long key = buf[g];
                    if (key <= T) {
                        float d2 = __uint_as_float((unsigned)(key >> 11));
                        local += pair_energy(d2, (int)(key & 2047ull), seqb, aa_base);
                    }
                }
            } else {
                // --- Bucket overflow (never expected): discard, exact flat radix ---
                local = 0.f;
                if (tid == 0) { s_pref = 0ull; s_targ = KSEL; }
                __syncthreads();
                for (int pass = 0; pass < 6; pass++) {
                    const int shift = 40 - 8 * pass;
                    hist[tid] = 0;
                    __syncthreads();
                    const unsigned long long hp = s_pref >> (shift + 8);
                    for (int g = tid; g < ctot; g += 256) {
                        unsigned long long key = cand[g];
                        if ((key >> (shift + 8)) == hp)
                            atomicAdd(&hist[(int)((key >> shift) & 255)], 1);
                    }
                    __syncthreads();
                    if (tid < 32) {
                        const int base = tid * 8;
                        int c8[8]; int ssum = 0;
                        #pragma unroll
                        for (int t = 0; t < 8; t++) { c8[t] = hist[base + t]; ssum += c8[t]; }
                        int incl2 = ssum;
                        #pragma unroll
                        for (int o = 1; o < 32; o <<= 1) {
                            int t = __shfl_up_sync(0xffffffffu, incl2, o);
                            if (tid >= o) incl2 += t;
                        }
                        int excl2 = incl2 - ssum;
                        const int tgt = s_targ;
                        const unsigned long long pref = s_pref;
                        __syncwarp();
                        int run = excl2;
                        #pragma unroll
                        for (int t = 0; t < 8; t++) {
                            if (run < tgt && tgt <= run + c8[t]) {
                                s_pref = pref | ((unsigned long long)(base + t) << shift);
                                s_targ = tgt - run;
                            }
                            run += c8[t];
                        }
                    }
                    __syncthreads();
                }
                const unsigned long long T = s_pref;
                for (int g = tid; g < ctot; g += 256) {
                    unsigned long long key = cand[g];
                    if (key <= T) {
                        float d2 = __uint_as_float((unsigned)(key >> 11));
                        local += pair_energy(d2, (int)(key & 2047ull), seqb, aa_base);
                    }
                }
            }
        } else {
            // ctot <= KSEL: every candidate contributes
            for (int g = tid; g < ctot; g += 256) {
                unsigned long long key = cand[g];
                float d2 = __uint_as_float((unsigned)(key >> 11));
                local += pair_energy(d2, (int)(key & 2047ull), seqb, aa_base);
            }
        }
    } else {
        // ============ SLOW PATH (ctot > CANDN, never expected): R7 pipeline ============
        hist[tid] = 0;
        __syncthreads();
        #pragma unroll 1
        for (int s = 0; s < 8; s++) {
            const int cs = s_cnt[s];
            for (int c = tid; c < cs; c += 256) {
                float d2 = __uint_as_float((unsigned)(seg[(s << 8) + c] >> 11));
                atomicAdd(&hist[min((int)(d2 * BINSCALE), 255)], 1);
            }
        }
        __syncthreads();

        int v = hist[tid];
        int incl = v;
        #pragma unroll
        for (int o = 1; o < 32; o <<= 1) {
            int t = __shfl_up_sync(0xffffffffu, incl, o);
            if (lane >= o) incl += t;
        }
        if (lane == 31) wtot[w] = incl;
        __syncthreads();
        if (tid == 0) {
            int r = 0;
            #pragma unroll
            for (int q = 0; q < 8; q++) { int t = wtot[q]; wtot[q] = r; r += t; }
        }
        __syncthreads();
        incl += wtot[w];
        int excl = incl - v;
        if (excl < KSEL && KSEL <= incl) { s_B = tid; s_targ = KSEL - excl; }
        __syncthreads();
        const int B = s_B;

        #pragma unroll 1
        for (int s = 0; s < 8; s++) {
            const int cs = s_cnt[s];
            for (int c = tid; c < cs; c += 256) {
                unsigned long long key = seg[(s << 8) + c];
                float d2 = __uint_as_float((unsigned)(key >> 11));
                int bin = min((int)(d2 * BINSCALE), 255);
                if (bin == B) {
                    int pos = atomicAdd(&s_bcnt, 1);
                    if (pos < BCAP) buf[pos] = key;
                }
            }
        }
        __syncthreads();
        const int bc = s_bcnt;

        if (bc <= BCAP) {
            if (tid < 32) {
                const int tg = s_targ;
                for (int c = lane; c < bc; c += 32) {
                    unsigned long long key = buf[c];
                    int rank = 0;
                    for (int t = 0; t < bc; t++) rank += (buf[t] < key);
                    if (rank == tg - 1) s_T = key;
                }
            }
            __syncthreads();
        } else {
            if (tid == 0) { s_pref = 0ull; s_targ = KSEL; }
            __syncthreads();
            for (int pass = 0; pass < 6; pass++) {
                const int shift = 40 - 8 * pass;
                hist[tid] = 0;
                __syncthreads();
                const unsigned long long hp = s_pref >> (shift + 8);
                for (int s = 0; s < 8; s++) {
                    const int cs = s_cnt[s];
                    for (int c = tid; c < cs; c += 256) {
                        unsigned long long key = seg[(s << 8) + c];
                        if ((key >> (shift + 8)) == hp)
                            atomicAdd(&hist[(int)((key >> shift) & 255)], 1);
                    }
                }
                __syncthreads();
                if (tid < 32) {
                    const int base = tid * 8;
                    int c8[8]; int ssum = 0;
                    #pragma unroll
                    for (int t = 0; t < 8; t++) { c8[t] = hist[base + t]; ssum += c8[t]; }
                    int incl2 = ssum;
                    #pragma unroll
                    for (int o = 1; o < 32; o <<= 1) {
                        int t = __shfl_up_sync(0xffffffffu, incl2, o);
                        if (tid >= o) incl2 += t;
                    }
                    int excl2 = incl2 - ssum;
                    const int tgt = s_targ;
                    const unsigned long long pref = s_pref;
                    __syncwarp();
                    int run = excl2;
                    #pragma unroll
                    for (int t = 0; t < 8; t++) {
                        if (run < tgt && tgt <= run + c8[t]) {
                            s_pref = pref | ((unsigned long long)(base + t) << shift);
                            s_targ = tgt - run;
                        }
                        run += c8[t];
                    }
                }
                __syncthreads();
            }
            if (tid == 0) s_T = s_pref;
            __syncthreads();
        }

        const unsigned long long T = s_T;
        #pragma unroll 1
        for (int s = 0; s < 8; s++) {
            const int cs = s_cnt[s];
            for (int c = tid; c < cs; c += 256) {
                unsigned long long key = seg[(s << 8) + c];
                if (key <= T) {
                    float d2 = __uint_as_float((unsigned)(key >> 11));
                    local += pair_energy(d2, (int)(key & 2047ull), seqb, aa_base);
                }
            }
        }
    }

    // --- Deterministic block reduction ---
    #pragma unroll
    for (int o = 16; o > 0; o >>= 1)
        local += __shfl_down_sync(0xffffffffu, local, o);
    if (lane == 0) wsum[w] = local;
    __syncthreads();
    if (tid == 0) {
        float s = 0.f;
        #pragma unroll
        for (int q = 0; q < 8; q++) s += wsum[q];
        g_rowsum[row] = s;
    }
}

// ---------------------------------------------------------------------------
// Kernel 2: deterministic per-batch reduction
// ---------------------------------------------------------------------------
__global__ void __launch_bounds__(256) reduce_kernel(float* __restrict__ out)
{
    __shared__ float s[256];
    const int b = blockIdx.x;
    const int tid = threadIdx.x;
    float v = 0.f;
    for (int i = tid; i < Ln; i += 256) v += g_rowsum[b * Ln + i];
    s[tid] = v;
    __syncthreads();
    for (int o = 128; o > 0; o >>= 1) {
        if (tid < o) s[tid] += s[tid + o];
        __syncthreads();
    }
    if (tid == 0) out[b] = s[0];
}

// ---------------------------------------------------------------------------
extern "C" void kernel_launch(void* const* d_in, const int* in_sizes, int n_in,
                              void* d_out, int out_size)
{
    const float* R       = (const float*)d_in[0];
    const int*   seq     = (const int*)  d_in[1];
    const float* emb     = (const float*)d_in[2];
    const float* W1      = (const float*)d_in[3];
    const float* b1      = (const float*)d_in[4];
    const float* W2      = (const float*)d_in[5];
    const float* b2      = (const float*)d_in[6];
    const float* W3      = (const float*)d_in[7];
    const float* b3      = (const float*)d_in[8];
    float* out = (float*)d_out;

    table_kernel<<<NAA * NAA / 2, 512>>>(emb, W1, b1, W2, b2, W3, b3);
    topk_energy_kernel<<<Bn * Ln, 256>>>(R, seq);
    reduce_kernel<<<Bn, 256>>>(out);
}

// round 12
// speedup vs baseline: 1.8513x; 1.6387x over previous
#include <cuda_runtime.h>
#include <cuda_bf16.h>
#include <math.h>

#define Bn    8
#define Ln    2048
#define KSEL  64
#define EXCL  3
#define NAA   20
#define EMB   16
#define MD    7
#define D2CUT 144.0f      // r >= 12 -> smoothstep == 0 -> zero energy
#define BCAP  256         // bucket capacity before radix fallback
#define CANDN 1024        // flat candidate buffer (E[max] ~620, 19 sigma)
#define BINSCALE (256.0f / 144.0f)

// Scratch (device globals: no allocation allowed)
__device__ float g_rowsum[Bn * Ln];
__device__ float g_tab[NAA * NAA * MD];       // softplus(MLP(aa_i,aa_j))

// ---------------------------------------------------------------------------
// Kernel 0: exact fp32 MLP over 400 AA pairs -> 400x7 table.
// 2 pairs/block (ILP-2), 512 threads, 4-way K-split (short serial chains).
// ---------------------------------------------------------------------------
__global__ void __launch_bounds__(512) table_kernel(
    const float* __restrict__ emb,
    const float* __restrict__ W1, const float* __restrict__ b1,
    const float* __restrict__ W2, const float* __restrict__ b2,
    const float* __restrict__ W3, const float* __restrict__ b3)
{
    __shared__ float x[2][48];
    __shared__ float h1[2][128];
    __shared__ float h2[2][128];
    __shared__ float part[2][4][128];

    const int p0 = blockIdx.x * 2;
    const int tid = threadIdx.x;
    const int n = tid & 127;
    const int q4 = tid >> 7;            // 0..3

    if (tid < 2 * EMB) {
        int pr = tid >> 4, c = tid & 15;
        int p = p0 + pr;
        float ei = emb[(p / NAA) * EMB + c];
        float ej = emb[(p % NAA) * EMB + c];
        x[pr][c] = ei; x[pr][EMB + c] = ej; x[pr][2 * EMB + c] = ei * ej;
    }
    __syncthreads();

    {   // Layer 1: K=48, 4 x 12
        float a0 = 0.f, a1 = 0.f;
        const int k0 = q4 * 12;
        #pragma unroll
        for (int k = 0; k < 12; k++) {
            float w = W1[(k0 + k) * 128 + n];
            a0 = fmaf(x[0][k0 + k], w, a0);
            a1 = fmaf(x[1][k0 + k], w, a1);
        }
        part[0][q4][n] = a0; part[1][q4][n] = a1;
    }
    __syncthreads();
    if (q4 < 2)
        h1[q4][n] = fmaxf(b1[n] + part[q4][0][n] + part[q4][1][n]
                                + part[q4][2][n] + part[q4][3][n], 0.f);
    __syncthreads();

    {   // Layer 2: K=128, 4 x 32
        float a0 = 0.f, a1 = 0.f;
        const int k0 = q4 * 32;
        #pragma unroll
        for (int k = 0; k < 32; k++) {
            float w = W2[(k0 + k) * 128 + n];
            a0 = fmaf(h1[0][k0 + k], w, a0);
            a1 = fmaf(h1[1][k0 + k], w, a1);
        }
        part[0][q4][n] = a0; part[1][q4][n] = a1;
    }
    __syncthreads();
    if (q4 < 2)
        h2[q4][n] = fmaxf(b2[n] + part[q4][0][n] + part[q4][1][n]
                                + part[q4][2][n] + part[q4][3][n], 0.f);
    __syncthreads();

    if (tid < 2 * MD * 4) {   // Layer 3: K=128, 4 x 32, 7 outs x 2 pairs
        int pr = tid / 28, rem = tid % 28;
        int m = rem % MD, qq = rem / MD;
        float a = 0.f;
        const int k0 = qq * 32;
        #pragma unroll
        for (int k = 0; k < 32; k++)
            a = fmaf(h2[pr][k0 + k], W3[(k0 + k) * MD + m], a);
        part[pr][qq][m] = a;
    }
    __syncthreads();
    if (tid < 2 * MD) {
        int pr = tid / MD, m = tid % MD;
        float a = b3[m] + part[pr][0][m] + part[pr][1][m]
                        + part[pr][2][m] + part[pr][3][m];
        float sp = fmaxf(a, 0.f) + log1pf(expf(-fabsf(a)));  // jax softplus
        g_tab[(p0 + pr) * MD + m] = sp;
    }
}

// ---------------------------------------------------------------------------
// Per-pair energy: table lookup + anchored RBF product chain + smoothstep.
// ---------------------------------------------------------------------------
__device__ __forceinline__ float pair_energy(float d2, int jj,
                                             const int* __restrict__ seqb,
                                             int aa_base)
{
    float r = sqrtf(d2);
    int aj = __ldg(seqb + jj);
    const float* tp = g_tab + (aa_base + aj) * MD;
    const float C2  = 0.13533528323661270f;      // e^-2
    const float C6  = 2.4787521766663585e-3f;    // e^-6
    const float C10 = 4.5399929762484854e-5f;    // e^-10
    float t  = r - 8.f;
    float p3 = __expf(-2.f * t * t);
    float G  = __expf( 4.f * t);
    float Gi = __expf(-4.f * t);
    float p4 = p3 * G  * C2;
    float p5 = p4 * G  * C6;
    float p6 = p5 * G  * C10;
    float p2 = p3 * Gi * C2;
    float p1 = p2 * Gi * C6;
    float p0 = p1 * Gi * C10;
    float att = tp[0] * p0 + tp[1] * p1 + tp[2] * p2 + tp[3] * p3
              + tp[4] * p4 + tp[5] * p5 + tp[6] * p6;
    float tt = fminf(fmaxf((r - 10.f) * 0.5f, 0.f), 1.f);
    float sw = 1.f - tt * tt * (3.f - 2.f * tt);
    return -att * sw;
}

// ---------------------------------------------------------------------------
// Kernel 1: one row per CTA. R7 scan (proven) + flat-compacted select.
// __launch_bounds__(256, 8) pins 8 CTAs/SM (<=32 regs).
// key = (bits(d2) << 11) | j  (43 bits, unique). Exact fallbacks retained.
// ---------------------------------------------------------------------------
__global__ void __launch_bounds__(256, 8) topk_energy_kernel(
    const float* __restrict__ R, const int* __restrict__ seq)
{
    __shared__ unsigned long long seg[8 * 256];    // 16 KB
    __shared__ unsigned long long cand[CANDN];     // 8 KB
    __shared__ unsigned long long buf[BCAP];       // 2 KB
    __shared__ int hist[256];
    __shared__ int s_cnt[8];
    __shared__ int wtot[8];
    __shared__ float wsum[8];
    __shared__ int s_B, s_targ, s_bcnt;
    __shared__ unsigned long long s_T;
    __shared__ unsigned long long s_pref;

    const int tid = threadIdx.x;
    const int w = tid >> 5, lane = tid & 31;
    const unsigned lanelt = (1u << lane) - 1u;
    const int row = blockIdx.x;
    const int b = row >> 11;
    const int i = row & (Ln - 1);
    const float* __restrict__ Rb = R + (size_t)b * Ln * 3;
    const int* __restrict__ seqb = seq + b * Ln;

    const float xi = Rb[3 * i], yi = Rb[3 * i + 1], zi = Rb[3 * i + 2];

    if (tid == 0) { s_bcnt = 0; s_T = ~0ull; }

    // --- Scan: warp w owns j in [256w, 256w+256), ballot compaction ---
    int cnt = 0;
    #pragma unroll
    for (int it = 0; it < 8; it++) {
        const int j = (w << 8) + (it << 5) + lane;
        float dx = xi - Rb[3 * j];
        float dy = yi - Rb[3 * j + 1];
        float dz = zi - Rb[3 * j + 2];
        float d2 = fmaf(dx, dx, fmaf(dy, dy, fmaf(dz, dz, 1e-12f)));
        bool p = (d2 < D2CUT) && ((unsigned)(j - i + EXCL) > 2u * EXCL);
        unsigned m = __ballot_sync(0xffffffffu, p);
        if (p) {
            seg[(w << 8) + cnt + __popc(m & lanelt)] =
                (((unsigned long long)__float_as_uint(d2)) << 11) | (unsigned)j;
        }
        cnt += __popc(m);
    }
    if (lane == 0) s_cnt[w] = cnt;
    __syncthreads();

    int ctot = 0;
    #pragma unroll
    for (int s = 0; s < 8; s++) ctot += s_cnt[s];

    const int aa_base = __ldg(seqb + i) * NAA;
    float local = 0.f;

    if (ctot <= CANDN) {
        // ===================== FLAT FAST PATH =====================
        {
            int off = 0;
            #pragma unroll
            for (int s = 0; s < 8; s++) {
                int cs = s_cnt[s];
                if (tid < cs) cand[off + tid] = seg[(s << 8) + tid];
                off += cs;
            }
        }
        hist[tid] = 0;
        __syncthreads();

        if (ctot > KSEL) {
            // --- 1-round 256-bin linear-d2 histogram ---
            for (int g = tid; g < ctot; g += 256) {
                float d2 = __uint_as_float((unsigned)(cand[g] >> 11));
                atomicAdd(&hist[min((int)(d2 * BINSCALE), 255)], 1);
            }
            __syncthreads();

            // --- Block inclusive scan over bins, find crossing bin ---
            int v = hist[tid];
            int incl = v;
            #pragma unroll
            for (int o = 1; o < 32; o <<= 1) {
                int t = __shfl_up_sync(0xffffffffu, incl, o);
                if (lane >= o) incl += t;
            }
            if (lane == 31) wtot[w] = incl;
            __syncthreads();
            if (tid == 0) {
                int r = 0;
                #pragma unroll
                for (int q = 0; q < 8; q++) { int t = wtot[q]; wtot[q] = r; r += t; }
            }
            __syncthreads();
            incl += wtot[w];
            int excl = incl - v;
            if (excl < KSEL && KSEL <= incl) { s_B = tid; s_targ = KSEL - excl; }
            __syncthreads();
            const int B = s_B;

            // --- Gather bucket + fused below-bucket energy ---
            for (int g = tid; g < ctot; g += 256) {
                unsigned long long key = cand[g];
                float d2 = __uint_as_float((unsigned)(key >> 11));
                int bin = min((int)(d2 * BINSCALE), 255);
                if (bin < B) {
                    local += pair_energy(d2, (int)(key & 2047ull), seqb, aa_base);
                } else if (bin == B) {
                    int pos = atomicAdd(&s_bcnt, 1);
                    if (pos < BCAP) buf[pos] = key;
                }
            }
            __syncthreads();
            const int bc = s_bcnt;

            if (bc <= BCAP) {
                // --- Exact threshold by warp-0 rank count (unique keys) ---
                if (tid < 32) {
                    const int tg = s_targ;
                    for (int c = lane; c < bc; c += 32) {
                        unsigned long long key = buf[c];
                        int rank = 0;
                        for (int t = 0; t < bc; t++) rank += (buf[t] < key);
                        if (rank == tg - 1) s_T = key;
                    }
                }
                __syncthreads();
                const unsigned long long T = s_T;
                for (int g = tid; g < bc; g += 256) {
                    unsigned long long key = buf[g];
                    if (key <= T) {
                        float d2 = __uint_as_float((unsigned)(key >> 11));
                        local += pair_energy(d2, (int)(key & 2047ull), seqb, aa_base);
                    }
                }
            } else {
                // --- Bucket overflow (never expected): exact flat radix ---
                local = 0.f;
                if (tid == 0) { s_pref = 0ull; s_targ = KSEL; }
                __syncthreads();
                for (int pass = 0; pass < 6; pass++) {
                    const int shift = 40 - 8 * pass;
                    hist[tid] = 0;
                    __syncthreads();
                    const unsigned long long hp = s_pref >> (shift + 8);
                    for (int g = tid; g < ctot; g += 256) {
                        unsigned long long key = cand[g];
                        if ((key >> (shift + 8)) == hp)
                            atomicAdd(&hist[(int)((key >> shift) & 255)], 1);
                    }
                    __syncthreads();
                    if (tid < 32) {
                        const int base = tid * 8;
                        int c8[8]; int ssum = 0;
                        #pragma unroll
                        for (int t = 0; t < 8; t++) { c8[t] = hist[base + t]; ssum += c8[t]; }
                        int incl2 = ssum;
                        #pragma unroll
                        for (int o = 1; o < 32; o <<= 1) {
                            int t = __shfl_up_sync(0xffffffffu, incl2, o);
                            if (tid >= o) incl2 += t;
                        }
                        int excl2 = incl2 - ssum;
                        const int tgt = s_targ;
                        const unsigned long long pref = s_pref;
                        __syncwarp();
                        int run = excl2;
                        #pragma unroll
                        for (int t = 0; t < 8; t++) {
                            if (run < tgt && tgt <= run + c8[t]) {
                                s_pref = pref | ((unsigned long long)(base + t) << shift);
                                s_targ = tgt - run;
                            }
                            run += c8[t];
                        }
                    }
                    __syncthreads();
                }
                const unsigned long long T = s_pref;
                for (int g = tid; g < ctot; g += 256) {
                    unsigned long long key = cand[g];
                    if (key <= T) {
                        float d2 = __uint_as_float((unsigned)(key >> 11));
                        local += pair_energy(d2, (int)(key & 2047ull), seqb, aa_base);
                    }
                }
            }
        } else {
            // ctot <= KSEL: every candidate contributes
            for (int g = tid; g < ctot; g += 256) {
                unsigned long long key = cand[g];
                float d2 = __uint_as_float((unsigned)(key >> 11));
                local += pair_energy(d2, (int)(key & 2047ull), seqb, aa_base);
            }
        }
    } else {
        // ===== SLOW PATH (ctot > CANDN, never expected): segment-major =====
        hist[tid] = 0;
        __syncthreads();
        #pragma unroll 1
        for (int s = 0; s < 8; s++) {
            const int cs = s_cnt[s];
            for (int c = tid; c < cs; c += 256) {
                float d2 = __uint_as_float((unsigned)(seg[(s << 8) + c] >> 11));
                atomicAdd(&hist[min((int)(d2 * BINSCALE), 255)], 1);
            }
        }
        __syncthreads();

        int v = hist[tid];
        int incl = v;
        #pragma unroll
        for (int o = 1; o < 32; o <<= 1) {
            int t = __shfl_up_sync(0xffffffffu, incl, o);
            if (lane >= o) incl += t;
        }
        if (lane == 31) wtot[w] = incl;
        __syncthreads();
        if (tid == 0) {
            int r = 0;
            #pragma unroll
            for (int q = 0; q < 8; q++) { int t = wtot[q]; wtot[q] = r; r += t; }
        }
        __syncthreads();
        incl += wtot[w];
        int excl = incl - v;
        if (excl < KSEL && KSEL <= incl) { s_B = tid; s_targ = KSEL - excl; }
        __syncthreads();
        const int B = s_B;

        #pragma unroll 1
        for (int s = 0; s < 8; s++) {
            const int cs = s_cnt[s];
            for (int c = tid; c < cs; c += 256) {
                unsigned long long key = seg[(s << 8) + c];
                float d2 = __uint_as_float((unsigned)(key >> 11));
                int bin = min((int)(d2 * BINSCALE), 255);
                if (bin == B) {
                    int pos = atomicAdd(&s_bcnt, 1);
                    if (pos < BCAP) buf[pos] = key;
                }
            }
        }
        __syncthreads();
        const int bc = s_bcnt;

        if (bc <= BCAP) {
            if (tid < 32) {
                const int tg = s_targ;
                for (int c = lane; c < bc; c += 32) {
                    unsigned long long key = buf[c];
                    int rank = 0;
                    for (int t = 0; t < bc; t++) rank += (buf[t] < key);
                    if (rank == tg - 1) s_T = key;
                }
            }
            __syncthreads();
        } else {
            if (tid == 0) { s_pref = 0ull; s_targ = KSEL; }
            __syncthreads();
            for (int pass = 0; pass < 6; pass++) {
                const int shift = 40 - 8 * pass;
                hist[tid] = 0;
                __syncthreads();
                const unsigned long long hp = s_pref >> (shift + 8);
                for (int s = 0; s < 8; s++) {
                    const int cs = s_cnt[s];
                    for (int c = tid; c < cs; c += 256) {
                        unsigned long long key = seg[(s << 8) + c];
                        if ((key >> (shift + 8)) == hp)
                            atomicAdd(&hist[(int)((key >> shift) & 255)], 1);
                    }
                }
                __syncthreads();
                if (tid < 32) {
                    const int base = tid * 8;
                    int c8[8]; int ssum = 0;
                    #pragma unroll
                    for (int t = 0; t < 8; t++) { c8[t] = hist[base + t]; ssum += c8[t]; }
                    int incl2 = ssum;
                    #pragma unroll
                    for (int o = 1; o < 32; o <<= 1) {
                        int t = __shfl_up_sync(0xffffffffu, incl2, o);
                        if (tid >= o) incl2 += t;
                    }
                    int excl2 = incl2 - ssum;
                    const int tgt = s_targ;
                    const unsigned long long pref = s_pref;
                    __syncwarp();
                    int run = excl2;
                    #pragma unroll
                    for (int t = 0; t < 8; t++) {
                        if (run < tgt && tgt <= run + c8[t]) {
                            s_pref = pref | ((unsigned long long)(base + t) << shift);
                            s_targ = tgt - run;
                        }
                        run += c8[t];
                    }
                }
                __syncthreads();
            }
            if (tid == 0) s_T = s_pref;
            __syncthreads();
        }

        const unsigned long long T = s_T;
        #pragma unroll 1
        for (int s = 0; s < 8; s++) {
            const int cs = s_cnt[s];
            for (int c = tid; c < cs; c += 256) {
                unsigned long long key = seg[(s << 8) + c];
                if (key <= T) {
                    float d2 = __uint_as_float((unsigned)(key >> 11));
                    local += pair_energy(d2, (int)(key & 2047ull), seqb, aa_base);
                }
            }
        }
    }

    // --- Deterministic block reduction ---
    #pragma unroll
    for (int o = 16; o > 0; o >>= 1)
        local += __shfl_down_sync(0xffffffffu, local, o);
    if (lane == 0) wsum[w] = local;
    __syncthreads();
    if (tid == 0) {
        float s = 0.f;
        #pragma unroll
        for (int q = 0; q < 8; q++) s += wsum[q];
        g_rowsum[row] = s;
    }
}

// ---------------------------------------------------------------------------
// Kernel 2: deterministic per-batch reduction
// ---------------------------------------------------------------------------
__global__ void __launch_bounds__(256) reduce_kernel(float* __restrict__ out)
{
    __shared__ float s[256];
    const int b = blockIdx.x;
    const int tid = threadIdx.x;
    float v = 0.f;
    for (int i = tid; i < Ln; i += 256) v += g_rowsum[b * Ln + i];
    s[tid] = v;
    __syncthreads();
    for (int o = 128; o > 0; o >>= 1) {
        if (tid < o) s[tid] += s[tid + o];
        __syncthreads();
    }
    if (tid == 0) out[b] = s[0];
}

// ---------------------------------------------------------------------------
extern "C" void kernel_launch(void* const* d_in, const int* in_sizes, int n_in,
                              void* d_out, int out_size)
{
    const float* R       = (const float*)d_in[0];
    const int*   seq     = (const int*)  d_in[1];
    const float* emb     = (const float*)d_in[2];
    const float* W1      = (const float*)d_in[3];
    const float* b1      = (const float*)d_in[4];
    const float* W2      = (const float*)d_in[5];
    const float* b2      = (const float*)d_in[6];
    const float* W3      = (const float*)d_in[7];
    const float* b3      = (const float*)d_in[8];
    float* out = (float*)d_out;

    table_kernel<<<NAA * NAA / 2, 512>>>(emb, W1, b1, W2, b2, W3, b3);
    topk_energy_kernel<<<Bn * Ln, 256>>>(R, seq);
    reduce_kernel<<<Bn, 256>>>(out);
}